// round 9
// baseline (speedup 1.0000x reference)
#include <cuda_runtime.h>
#include <cuda_fp16.h>

#define NN 12288
#define NE 393216
#define EPSF 1e-8f
#define CAPN 192          // fixed bucket capacity per node (deg ~ Poisson(64))
#define LCAP 16           // per-warp conflict-list capacity (dups ~0.16/node)

// ---- scratch (static device globals; no allocation in kernel_launch) ----
__device__ float4 g_wp[64 * 32];                // packed (WsT, WsT+32, WnT, WnT+32)
__device__ __half g_xnh[NN * 64];               // fp16 x/||x|| (edge cosines)
__device__ float  g_an[NN * 64];                // fp32 normalize(x @ Wn^T)
__device__ float  g_sf[NN * 64];                // fp32 normalize(x @ Ws^T)
__device__ unsigned int g_cur[NN];              // per-node fill counters
__device__ unsigned long long g_ent[NN * CAPN]; // packed (key20 | w30 | j14)
__device__ unsigned int g_pay[NN * CAPN];       // packed (fp16(w)<<16 | j14)

__device__ __forceinline__ float wred(float v) {
#pragma unroll
    for (int o = 16; o; o >>= 1) v += __shfl_xor_sync(0xffffffffu, v, o);
    return v;
}
__device__ __forceinline__ float entw(unsigned long long pe) {
    return __uint_as_float(((unsigned int)(pe >> 14) & 0x3FFFFFFFu) << 2);
}
__device__ __forceinline__ float payw(unsigned int p) {
    return __half2float(__ushort_as_half((unsigned short)(p >> 16)));
}

// ---------------------------------------------------------------------------
// Prep: repack W into interleaved float4 (L1-resident afterwards) + zero g_cur.
// ---------------------------------------------------------------------------
__global__ void k_prep(const float* __restrict__ Ws, const float* __restrict__ Wn) {
    int t = blockIdx.x * blockDim.x + threadIdx.x;
    if (t < NN) g_cur[t] = 0u;
    if (t < 2048) {
        int k = t >> 5, l = t & 31;
        g_wp[k * 32 + l] = make_float4(Ws[l * 64 + k], Ws[(l + 32) * 64 + k],
                                       Wn[l * 64 + k], Wn[(l + 32) * 64 + k]);
    }
}

// ---------------------------------------------------------------------------
// 2 nodes per warp, 128-thread blocks. W via coalesced LDG.128 (L1-hit),
// x broadcast from tiny per-warp smem.
// ---------------------------------------------------------------------------
__global__ __launch_bounds__(128) void k_transform(const float* __restrict__ x) {
    __shared__ float sx[4][2][64];     // [warp][node][k]
    int warp = threadIdx.x >> 5, lane = threadIdx.x & 31;
    int i0 = blockIdx.x * 8 + warp * 2;

    float xa0[2], xa1[2];
#pragma unroll
    for (int n = 0; n < 2; n++) {
        xa0[n] = x[(i0 + n) * 64 + lane];
        xa1[n] = x[(i0 + n) * 64 + 32 + lane];
        sx[warp][n][lane]      = xa0[n];
        sx[warp][n][32 + lane] = xa1[n];
    }
    __syncwarp();

    float s0[2] = {0, 0}, s1[2] = {0, 0}, a0[2] = {0, 0}, a1[2] = {0, 0};
#pragma unroll
    for (int kb = 0; kb < 16; kb++) {
        float4 w0 = __ldg(&g_wp[(kb * 4 + 0) * 32 + lane]);
        float4 w1 = __ldg(&g_wp[(kb * 4 + 1) * 32 + lane]);
        float4 w2 = __ldg(&g_wp[(kb * 4 + 2) * 32 + lane]);
        float4 w3 = __ldg(&g_wp[(kb * 4 + 3) * 32 + lane]);
#pragma unroll
        for (int n = 0; n < 2; n++) {
            float4 xq = *(const float4*)&sx[warp][n][kb * 4];  // LDS.128 broadcast
            s0[n] += xq.x * w0.x + xq.y * w1.x + xq.z * w2.x + xq.w * w3.x;
            s1[n] += xq.x * w0.y + xq.y * w1.y + xq.z * w2.y + xq.w * w3.y;
            a0[n] += xq.x * w0.z + xq.y * w1.z + xq.z * w2.z + xq.w * w3.z;
            a1[n] += xq.x * w0.w + xq.y * w1.w + xq.z * w2.w + xq.w * w3.w;
        }
    }
#pragma unroll
    for (int n = 0; n < 2; n++) {
        int i = i0 + n;
        float nx = wred(xa0[n] * xa0[n] + xa1[n] * xa1[n]);
        float ns = wred(s0[n] * s0[n] + s1[n] * s1[n]);
        float na = wred(a0[n] * a0[n] + a1[n] * a1[n]);
        float rx = 1.f / sqrtf(nx);
        float rs = 1.f / (sqrtf(ns) + EPSF);
        float ra = 1.f / (sqrtf(na) + EPSF);
        g_xnh[i * 64 + lane]      = __float2half_rn(xa0[n] * rx);
        g_xnh[i * 64 + 32 + lane] = __float2half_rn(xa1[n] * rx);
        g_an[i * 64 + lane]       = a0[n] * ra;
        g_an[i * 64 + 32 + lane]  = a1[n] * ra;
        g_sf[i * 64 + lane]       = s0[n] * rs;
        g_sf[i * 64 + 32 + lane]  = s1[n] * rs;
    }
}

// ---------------------------------------------------------------------------
// 4 edges per warp, 8 lanes per edge. Cosine weight, then scatter both
// directed incidences (u64 key entry + u32 gather payload).
// key = k (pass-1 at (r,c)) or k+NE (pass-2 at (c,r)); max key = last writer.
// ---------------------------------------------------------------------------
__global__ __launch_bounds__(256) void k_edge(const int* __restrict__ ei) {
    int warp = threadIdx.x >> 5, lane = threadIdx.x & 31;
    int sub = lane >> 3, l8 = lane & 7;
    int k = blockIdx.x * 32 + warp * 4 + sub;
    int r = __ldg(&ei[k]);
    int c = __ldg(&ei[NE + k]);
    uint4 ur = *(const uint4*)(g_xnh + r * 64 + l8 * 8);
    uint4 uc = *(const uint4*)(g_xnh + c * 64 + l8 * 8);
    const __half2* hr = (const __half2*)&ur;
    const __half2* hc = (const __half2*)&uc;
    float d = 0.f;
#pragma unroll
    for (int q = 0; q < 4; q++) {
        float2 a = __half22float2(hr[q]);
        float2 b = __half22float2(hc[q]);
        d += a.x * b.x + a.y * b.y;
    }
#pragma unroll
    for (int o = 4; o; o >>= 1) d += __shfl_xor_sync(0xffffffffu, d, o);
    if (l8 == 0) {
        float w = fminf(fmaxf((d + 1.f) * 0.5f, 0.1f), 0.9f);
        unsigned long long w30 = (unsigned long long)(__float_as_uint(w) >> 2);
        unsigned int hw = (unsigned int)__half_as_ushort(__float2half_rn(w));
        unsigned long long e1 = ((unsigned long long)(unsigned)k << 44) | (w30 << 14) | (unsigned)c;
        unsigned long long e2 = ((unsigned long long)(unsigned)(k + NE) << 44) | (w30 << 14) | (unsigned)r;
        unsigned int p = atomicAdd(&g_cur[r], 1u);
        if (p < CAPN) { g_ent[r * CAPN + p] = e1; g_pay[r * CAPN + p] = (hw << 16) | (unsigned)c; }
        unsigned int q2 = atomicAdd(&g_cur[c], 1u);
        if (q2 < CAPN) { g_ent[c * CAPN + q2] = e2; g_pay[c * CAPN + q2] = (hw << 16) | (unsigned)r; }
    }
}

// ---------------------------------------------------------------------------
// One warp per node, 128-thread blocks. Phase A: payload staging + bitmap
// dup-detect. Phase B: fp32 gather, 8 entries/iter (2 independent chains),
// 8 lanes/entry, 2x LDG.128/lane — NO fp16 cvt in the hot loop. Self-add +
// exact max-key fixup (JAX .set semantics) after reduction.
// ---------------------------------------------------------------------------
__global__ __launch_bounds__(128) void k_agg(const float* __restrict__ bias,
                                             float* __restrict__ out) {
    __shared__ unsigned int bm[4][384];        // 12288-bit presence map per warp
    __shared__ unsigned int spay[4][CAPN + 8];
    __shared__ int cj[4][LCAP];
    __shared__ int ccnt[4];
    int warp = threadIdx.x >> 5, lane = threadIdx.x & 31;
    int sub = lane >> 3, l8 = lane & 7;
    int i = blockIdx.x * 4 + warp;

#pragma unroll
    for (int t = lane; t < 384; t += 32) bm[warp][t] = 0u;
    if (lane == 0) ccnt[warp] = 0;
    __syncwarp();

    int deg = (int)min(g_cur[i], (unsigned)CAPN);
    int selfF = 0;

    // Phase A: stage payloads + duplicate detection
    for (int base = 0; base < deg; base += 32) {
        int e = base + lane;
        if (e < deg) {
            unsigned int p = __ldg(&g_pay[i * CAPN + e]);
            spay[warp][e] = p;
            unsigned int j = p & 0x3FFFu;
            if (j == (unsigned)i) selfF = 1;
            unsigned int old = atomicOr(&bm[warp][j >> 5], 1u << (j & 31));
            if (old & (1u << (j & 31))) {
                int idx = atomicAdd(&ccnt[warp], 1);
                if (idx < LCAP) cj[warp][idx] = (int)j;
            }
        }
    }
    if (lane < 8) spay[warp][deg + lane] = 0u;   // zero-weight padding
    int hasSelf = (__ballot_sync(0xffffffffu, selfF) != 0u);
    __syncwarp();

    // Phase B: 8 entries/iter; lane handles entries t+sub and t+4+sub,
    // dims l8*8 .. l8*8+7 (two float4 loads per row half)
    float acc[8] = {0, 0, 0, 0, 0, 0, 0, 0};
    for (int t = 0; t < deg; t += 8) {
        unsigned int pA = spay[warp][t + sub];
        unsigned int pB = spay[warp][t + 4 + sub];
        float wA = payw(pA), wB = payw(pB);
        const float4* rA = (const float4*)(g_an + (pA & 0x3FFFu) * 64 + l8 * 8);
        const float4* rB = (const float4*)(g_an + (pB & 0x3FFFu) * 64 + l8 * 8);
        float4 a0 = rA[0], a1 = rA[1];
        float4 b0 = rB[0], b1 = rB[1];
        acc[0] += wA * a0.x + wB * b0.x;
        acc[1] += wA * a0.y + wB * b0.y;
        acc[2] += wA * a0.z + wB * b0.z;
        acc[3] += wA * a0.w + wB * b0.w;
        acc[4] += wA * a1.x + wB * b1.x;
        acc[5] += wA * a1.y + wB * b1.y;
        acc[6] += wA * a1.z + wB * b1.z;
        acc[7] += wA * a1.w + wB * b1.w;
    }
#pragma unroll
    for (int d = 0; d < 8; d++) {
        acc[d] += __shfl_xor_sync(0xffffffffu, acc[d], 8);
        acc[d] += __shfl_xor_sync(0xffffffffu, acc[d], 16);
    }

    // exact fixup for conflicted j's (rare): keep only the max-key writer
    int cc = min(ccnt[warp], LCAP);
    for (int t = 0; t < cc; t++) {
        int j = cj[warp][t];
        bool seen = false;
        for (int u2 = 0; u2 < t; u2++) if (cj[warp][u2] == j) { seen = true; break; }
        if (seen) continue;
        float wsum = 0.f;
        unsigned long long best = 0ULL;
        for (int base = 0; base < deg; base += 32) {
            int e = base + lane;
            unsigned long long pe = (e < deg) ? g_ent[i * CAPN + e] : 0ULL;
            if (pe && (int)(pe & 0x3FFFULL) == j) {
                wsum += __half2float(__float2half_rn(entw(pe)));  // match gather encoding
                best = max(best, pe);
            }
        }
        wsum = wred(wsum);
#pragma unroll
        for (int o = 16; o; o >>= 1) {
            unsigned long long v = __shfl_xor_sync(0xffffffffu, best, o);
            best = max(best, v);
        }
        float corr = wsum - __half2float(__float2half_rn(entw(best)));
        float4 f0 = *(const float4*)(g_an + j * 64 + l8 * 8);
        float4 f1 = *(const float4*)(g_an + j * 64 + l8 * 8 + 4);
        acc[0] -= corr * f0.x; acc[1] -= corr * f0.y;
        acc[2] -= corr * f0.z; acc[3] -= corr * f0.w;
        acc[4] -= corr * f1.x; acc[5] -= corr * f1.y;
        acc[6] -= corr * f1.z; acc[7] -= corr * f1.w;
    }
    if (!hasSelf) {   // eye diagonal survives only when no edge overwrote it
        float4 f0 = *(const float4*)(g_an + i * 64 + l8 * 8);
        float4 f1 = *(const float4*)(g_an + i * 64 + l8 * 8 + 4);
        acc[0] += f0.x; acc[1] += f0.y; acc[2] += f0.z; acc[3] += f0.w;
        acc[4] += f1.x; acc[5] += f1.y; acc[6] += f1.z; acc[7] += f1.w;
    }

    // epilogue (dims replicated 4x across sub-groups: norms = wred(.)/4)
    float bp[8];
    {
        float4 b0 = *(const float4*)(bias + l8 * 8);
        float4 b1 = *(const float4*)(bias + l8 * 8 + 4);
        bp[0] = b0.x; bp[1] = b0.y; bp[2] = b0.z; bp[3] = b0.w;
        bp[4] = b1.x; bp[5] = b1.y; bp[6] = b1.z; bp[7] = b1.w;
        float sb = 0.f;
#pragma unroll
        for (int d = 0; d < 8; d++) sb += bp[d] * bp[d];
        float nb = sqrtf(wred(sb) * 0.25f + 1.0f);   // ||[bias,1]||
#pragma unroll
        for (int d = 0; d < 8; d++) bp[d] /= nb;
    }
    float sq = 0.f;
#pragma unroll
    for (int d = 0; d < 8; d++) sq += acc[d] * acc[d];
    float na = wred(sq) * 0.25f;
    float rn = 1.f / (sqrtf(na) + EPSF);

    float sv[8];
    {
        float4 s0 = *(const float4*)(g_sf + i * 64 + l8 * 8);
        float4 s1 = *(const float4*)(g_sf + i * 64 + l8 * 8 + 4);
        sv[0] = s0.x; sv[1] = s0.y; sv[2] = s0.z; sv[3] = s0.w;
        sv[4] = s1.x; sv[5] = s1.y; sv[6] = s1.z; sv[7] = s1.w;
    }
    float u8[8]; float squ = 0.f;
#pragma unroll
    for (int d = 0; d < 8; d++) { u8[d] = 0.5f * (sv[d] + acc[d] * rn); squ += u8[d] * u8[d]; }
    float nu = wred(squ) * 0.25f;
    float ru = 1.f / (sqrtf(nu) + EPSF);
    float m8[8]; float sqm = 0.f;
#pragma unroll
    for (int d = 0; d < 8; d++) { m8[d] = 0.9f * u8[d] * ru + 0.1f * bp[d]; sqm += m8[d] * m8[d]; }
    float nm = wred(sqm) * 0.25f;
    float rm = 1.f / (sqrtf(nm) + EPSF);
    float nrm2 = sqrtf(nm) * rm;   // ~1
    float rf = rm / (nrm2 + EPSF);
    if (sub == 0) {
        float4 o0 = make_float4(m8[0] * rf, m8[1] * rf, m8[2] * rf, m8[3] * rf);
        float4 o1 = make_float4(m8[4] * rf, m8[5] * rf, m8[6] * rf, m8[7] * rf);
        *(float4*)(out + i * 64 + l8 * 8)     = o0;
        *(float4*)(out + i * 64 + l8 * 8 + 4) = o1;
    }
}

extern "C" void kernel_launch(void* const* d_in, const int* in_sizes, int n_in,
                              void* d_out, int out_size) {
    const float* x  = (const float*)d_in[0];
    const int*   ei = (const int*)d_in[1];
    const float* Ws = (const float*)d_in[2];
    const float* Wn = (const float*)d_in[3];
    const float* b  = (const float*)d_in[4];
    float* out = (float*)d_out;

    k_prep<<<NN / 256, 256>>>(Ws, Wn);
    k_transform<<<NN / 8, 128>>>(x);
    k_edge<<<NE / 32, 256>>>(ei);
    k_agg<<<NN / 4, 128>>>(b, out);
}

// round 10
// speedup vs baseline: 1.1088x; 1.1088x over previous
#include <cuda_runtime.h>
#include <cuda_fp16.h>

#define NN 12288
#define NE 393216
#define EPSF 1e-8f
#define CAPN 192          // fixed bucket capacity per node (deg ~ Poisson(64))
#define LCAP 16           // per-warp conflict-list capacity (dups ~0.16/node)

// ---- scratch (static device globals; no allocation in kernel_launch) ----
__device__ float4 g_wp[64 * 32];                // packed (WsT, WsT+32, WnT, WnT+32)
__device__ __half g_xnh[NN * 64];               // fp16 x/||x|| (edge cosines)
__device__ __half g_anh[NN * 64];               // fp16 normalize(x @ Wn^T)
__device__ float  g_sf[NN * 64];                // fp32 normalize(x @ Ws^T)
__device__ unsigned int g_cur[NN];              // per-node fill counters
__device__ unsigned long long g_ent[NN * CAPN]; // packed (key20 | w30 | j14)
__device__ unsigned int g_pay[NN * CAPN];       // packed (fp16(w)<<16 | j14)

__device__ __forceinline__ float wred(float v) {
#pragma unroll
    for (int o = 16; o; o >>= 1) v += __shfl_xor_sync(0xffffffffu, v, o);
    return v;
}
__device__ __forceinline__ float entw(unsigned long long pe) {
    return __uint_as_float(((unsigned int)(pe >> 14) & 0x3FFFFFFFu) << 2);
}
__device__ __forceinline__ float payw(unsigned int p) {
    return __half2float(__ushort_as_half((unsigned short)(p >> 16)));
}

// ---------------------------------------------------------------------------
// Prep: repack W into interleaved float4 (L1-resident afterwards) + zero g_cur.
// ---------------------------------------------------------------------------
__global__ void k_prep(const float* __restrict__ Ws, const float* __restrict__ Wn) {
    int t = blockIdx.x * blockDim.x + threadIdx.x;
    if (t < NN) g_cur[t] = 0u;
    if (t < 2048) {
        int k = t >> 5, l = t & 31;
        g_wp[k * 32 + l] = make_float4(Ws[l * 64 + k], Ws[(l + 32) * 64 + k],
                                       Wn[l * 64 + k], Wn[(l + 32) * 64 + k]);
    }
}

// ---------------------------------------------------------------------------
// 2 nodes per warp, 128-thread blocks. W via coalesced LDG.128 (L1-hit),
// x broadcast from tiny per-warp smem.
// ---------------------------------------------------------------------------
__global__ __launch_bounds__(128) void k_transform(const float* __restrict__ x) {
    __shared__ float sx[4][2][64];     // [warp][node][k]
    int warp = threadIdx.x >> 5, lane = threadIdx.x & 31;
    int i0 = blockIdx.x * 8 + warp * 2;

    float xa0[2], xa1[2];
#pragma unroll
    for (int n = 0; n < 2; n++) {
        xa0[n] = x[(i0 + n) * 64 + lane];
        xa1[n] = x[(i0 + n) * 64 + 32 + lane];
        sx[warp][n][lane]      = xa0[n];
        sx[warp][n][32 + lane] = xa1[n];
    }
    __syncwarp();

    float s0[2] = {0, 0}, s1[2] = {0, 0}, a0[2] = {0, 0}, a1[2] = {0, 0};
#pragma unroll
    for (int kb = 0; kb < 16; kb++) {
        float4 w0 = __ldg(&g_wp[(kb * 4 + 0) * 32 + lane]);
        float4 w1 = __ldg(&g_wp[(kb * 4 + 1) * 32 + lane]);
        float4 w2 = __ldg(&g_wp[(kb * 4 + 2) * 32 + lane]);
        float4 w3 = __ldg(&g_wp[(kb * 4 + 3) * 32 + lane]);
#pragma unroll
        for (int n = 0; n < 2; n++) {
            float4 xq = *(const float4*)&sx[warp][n][kb * 4];  // LDS.128 broadcast
            s0[n] += xq.x * w0.x + xq.y * w1.x + xq.z * w2.x + xq.w * w3.x;
            s1[n] += xq.x * w0.y + xq.y * w1.y + xq.z * w2.y + xq.w * w3.y;
            a0[n] += xq.x * w0.z + xq.y * w1.z + xq.z * w2.z + xq.w * w3.z;
            a1[n] += xq.x * w0.w + xq.y * w1.w + xq.z * w2.w + xq.w * w3.w;
        }
    }
#pragma unroll
    for (int n = 0; n < 2; n++) {
        int i = i0 + n;
        float nx = wred(xa0[n] * xa0[n] + xa1[n] * xa1[n]);
        float ns = wred(s0[n] * s0[n] + s1[n] * s1[n]);
        float na = wred(a0[n] * a0[n] + a1[n] * a1[n]);
        float rx = 1.f / sqrtf(nx);
        float rs = 1.f / (sqrtf(ns) + EPSF);
        float ra = 1.f / (sqrtf(na) + EPSF);
        g_xnh[i * 64 + lane]      = __float2half_rn(xa0[n] * rx);
        g_xnh[i * 64 + 32 + lane] = __float2half_rn(xa1[n] * rx);
        g_anh[i * 64 + lane]      = __float2half_rn(a0[n] * ra);
        g_anh[i * 64 + 32 + lane] = __float2half_rn(a1[n] * ra);
        g_sf[i * 64 + lane]       = s0[n] * rs;
        g_sf[i * 64 + 32 + lane]  = s1[n] * rs;
    }
}

// ---------------------------------------------------------------------------
// 8 edges per warp, 4 lanes per edge (4 independent LDG.128 chains per lane).
// Cosine weight, then scatter both directed incidences.
// key = k (pass-1 at (r,c)) or k+NE (pass-2 at (c,r)); max key = last writer.
// ---------------------------------------------------------------------------
__global__ __launch_bounds__(256) void k_edge(const int* __restrict__ ei) {
    int warp = threadIdx.x >> 5, lane = threadIdx.x & 31;
    int sub = lane >> 2, l4 = lane & 3;
    int k = blockIdx.x * 64 + warp * 8 + sub;
    int r = __ldg(&ei[k]);
    int c = __ldg(&ei[NE + k]);
    const __half* pr = g_xnh + r * 64 + l4 * 16;
    const __half* pc = g_xnh + c * 64 + l4 * 16;
    uint4 ur0 = *(const uint4*)(pr);
    uint4 ur1 = *(const uint4*)(pr + 8);
    uint4 uc0 = *(const uint4*)(pc);
    uint4 uc1 = *(const uint4*)(pc + 8);
    const __half2* hr0 = (const __half2*)&ur0;
    const __half2* hr1 = (const __half2*)&ur1;
    const __half2* hc0 = (const __half2*)&uc0;
    const __half2* hc1 = (const __half2*)&uc1;
    float d = 0.f;
#pragma unroll
    for (int q = 0; q < 4; q++) {
        float2 a0 = __half22float2(hr0[q]);
        float2 b0 = __half22float2(hc0[q]);
        float2 a1 = __half22float2(hr1[q]);
        float2 b1 = __half22float2(hc1[q]);
        d += a0.x * b0.x + a0.y * b0.y + a1.x * b1.x + a1.y * b1.y;
    }
#pragma unroll
    for (int o = 2; o; o >>= 1) d += __shfl_xor_sync(0xffffffffu, d, o);
    if (l4 == 0) {
        float w = fminf(fmaxf((d + 1.f) * 0.5f, 0.1f), 0.9f);
        unsigned long long w30 = (unsigned long long)(__float_as_uint(w) >> 2);
        unsigned int hw = (unsigned int)__half_as_ushort(__float2half_rn(w));
        unsigned long long e1 = ((unsigned long long)(unsigned)k << 44) | (w30 << 14) | (unsigned)c;
        unsigned long long e2 = ((unsigned long long)(unsigned)(k + NE) << 44) | (w30 << 14) | (unsigned)r;
        unsigned int p = atomicAdd(&g_cur[r], 1u);
        if (p < CAPN) { g_ent[r * CAPN + p] = e1; g_pay[r * CAPN + p] = (hw << 16) | (unsigned)c; }
        unsigned int q2 = atomicAdd(&g_cur[c], 1u);
        if (q2 < CAPN) { g_ent[c * CAPN + q2] = e2; g_pay[c * CAPN + q2] = (hw << 16) | (unsigned)r; }
    }
}

// ---------------------------------------------------------------------------
// One warp per node, 128-thread blocks, min 12 blocks/SM (48 warps -> better
// latency hiding). Phase A: payload staging + bitmap dup-detect. Phase B:
// fp16 gather, 16 entries/iter (4 independent LDG.128 chains), 8 lanes/entry.
// Self-add + exact max-key fixup (JAX .set semantics) after reduction.
// ---------------------------------------------------------------------------
__global__ __launch_bounds__(128, 12) void k_agg(const float* __restrict__ bias,
                                                 float* __restrict__ out) {
    __shared__ unsigned int bm[4][384];        // 12288-bit presence map per warp
    __shared__ unsigned int spay[4][CAPN + 16];
    __shared__ int cj[4][LCAP];
    __shared__ int ccnt[4];
    int warp = threadIdx.x >> 5, lane = threadIdx.x & 31;
    int sub = lane >> 3, l8 = lane & 7;
    int i = blockIdx.x * 4 + warp;

#pragma unroll
    for (int t = lane; t < 384; t += 32) bm[warp][t] = 0u;
    if (lane == 0) ccnt[warp] = 0;
    __syncwarp();

    int deg = (int)min(g_cur[i], (unsigned)CAPN);
    int selfF = 0;

    // Phase A: stage payloads + duplicate detection
    for (int base = 0; base < deg; base += 32) {
        int e = base + lane;
        if (e < deg) {
            unsigned int p = __ldg(&g_pay[i * CAPN + e]);
            spay[warp][e] = p;
            unsigned int j = p & 0x3FFFu;
            if (j == (unsigned)i) selfF = 1;
            unsigned int old = atomicOr(&bm[warp][j >> 5], 1u << (j & 31));
            if (old & (1u << (j & 31))) {
                int idx = atomicAdd(&ccnt[warp], 1);
                if (idx < LCAP) cj[warp][idx] = (int)j;
            }
        }
    }
    if (lane < 16) spay[warp][deg + lane] = 0u;   // zero-weight padding
    int hasSelf = (__ballot_sync(0xffffffffu, selfF) != 0u);
    __syncwarp();

    // Phase B: 16 entries/iter; lane handles entries t+sub, t+4+sub, t+8+sub, t+12+sub
    float acc[8] = {0, 0, 0, 0, 0, 0, 0, 0};
    for (int t = 0; t < deg; t += 16) {
        unsigned int pA = spay[warp][t + sub];
        unsigned int pB = spay[warp][t + 4 + sub];
        unsigned int pC = spay[warp][t + 8 + sub];
        unsigned int pD = spay[warp][t + 12 + sub];
        float wA = payw(pA), wB = payw(pB), wC = payw(pC), wD = payw(pD);
        uint4 uA = *(const uint4*)(g_anh + (pA & 0x3FFFu) * 64 + l8 * 8);
        uint4 uB = *(const uint4*)(g_anh + (pB & 0x3FFFu) * 64 + l8 * 8);
        uint4 uC = *(const uint4*)(g_anh + (pC & 0x3FFFu) * 64 + l8 * 8);
        uint4 uD = *(const uint4*)(g_anh + (pD & 0x3FFFu) * 64 + l8 * 8);
        const __half2* hA = (const __half2*)&uA;
        const __half2* hB = (const __half2*)&uB;
        const __half2* hC = (const __half2*)&uC;
        const __half2* hD = (const __half2*)&uD;
#pragma unroll
        for (int q = 0; q < 4; q++) {
            float2 fA = __half22float2(hA[q]);
            float2 fB = __half22float2(hB[q]);
            float2 fC = __half22float2(hC[q]);
            float2 fD = __half22float2(hD[q]);
            acc[2 * q]     += wA * fA.x + wB * fB.x + wC * fC.x + wD * fD.x;
            acc[2 * q + 1] += wA * fA.y + wB * fB.y + wC * fC.y + wD * fD.y;
        }
    }
#pragma unroll
    for (int d = 0; d < 8; d++) {
        acc[d] += __shfl_xor_sync(0xffffffffu, acc[d], 8);
        acc[d] += __shfl_xor_sync(0xffffffffu, acc[d], 16);
    }

    // exact fixup for conflicted j's (rare): keep only the max-key writer
    int cc = min(ccnt[warp], LCAP);
    for (int t = 0; t < cc; t++) {
        int j = cj[warp][t];
        bool seen = false;
        for (int u2 = 0; u2 < t; u2++) if (cj[warp][u2] == j) { seen = true; break; }
        if (seen) continue;
        float wsum = 0.f;
        unsigned long long best = 0ULL;
        for (int base = 0; base < deg; base += 32) {
            int e = base + lane;
            unsigned long long pe = (e < deg) ? g_ent[i * CAPN + e] : 0ULL;
            if (pe && (int)(pe & 0x3FFFULL) == j) {
                wsum += __half2float(__float2half_rn(entw(pe)));  // match gather encoding
                best = max(best, pe);
            }
        }
        wsum = wred(wsum);
#pragma unroll
        for (int o = 16; o; o >>= 1) {
            unsigned long long v = __shfl_xor_sync(0xffffffffu, best, o);
            best = max(best, v);
        }
        float corr = wsum - __half2float(__float2half_rn(entw(best)));
        uint4 u = *(const uint4*)(g_anh + j * 64 + l8 * 8);
        const __half2* h = (const __half2*)&u;
#pragma unroll
        for (int q = 0; q < 4; q++) {
            float2 f = __half22float2(h[q]);
            acc[2 * q]     -= corr * f.x;
            acc[2 * q + 1] -= corr * f.y;
        }
    }
    if (!hasSelf) {   // eye diagonal survives only when no edge overwrote it
        uint4 u = *(const uint4*)(g_anh + i * 64 + l8 * 8);
        const __half2* h = (const __half2*)&u;
#pragma unroll
        for (int q = 0; q < 4; q++) {
            float2 f = __half22float2(h[q]);
            acc[2 * q]     += f.x;
            acc[2 * q + 1] += f.y;
        }
    }

    // epilogue (dims replicated 4x across sub-groups: norms = wred(.)/4)
    float bp[8];
    {
        float4 b0 = *(const float4*)(bias + l8 * 8);
        float4 b1 = *(const float4*)(bias + l8 * 8 + 4);
        bp[0] = b0.x; bp[1] = b0.y; bp[2] = b0.z; bp[3] = b0.w;
        bp[4] = b1.x; bp[5] = b1.y; bp[6] = b1.z; bp[7] = b1.w;
        float sb = 0.f;
#pragma unroll
        for (int d = 0; d < 8; d++) sb += bp[d] * bp[d];
        float nb = sqrtf(wred(sb) * 0.25f + 1.0f);   // ||[bias,1]||
#pragma unroll
        for (int d = 0; d < 8; d++) bp[d] /= nb;
    }
    float sq = 0.f;
#pragma unroll
    for (int d = 0; d < 8; d++) sq += acc[d] * acc[d];
    float na = wred(sq) * 0.25f;
    float rn = 1.f / (sqrtf(na) + EPSF);

    float sv[8];
    {
        float4 s0 = *(const float4*)(g_sf + i * 64 + l8 * 8);
        float4 s1 = *(const float4*)(g_sf + i * 64 + l8 * 8 + 4);
        sv[0] = s0.x; sv[1] = s0.y; sv[2] = s0.z; sv[3] = s0.w;
        sv[4] = s1.x; sv[5] = s1.y; sv[6] = s1.z; sv[7] = s1.w;
    }
    float u8[8]; float squ = 0.f;
#pragma unroll
    for (int d = 0; d < 8; d++) { u8[d] = 0.5f * (sv[d] + acc[d] * rn); squ += u8[d] * u8[d]; }
    float nu = wred(squ) * 0.25f;
    float ru = 1.f / (sqrtf(nu) + EPSF);
    float m8[8]; float sqm = 0.f;
#pragma unroll
    for (int d = 0; d < 8; d++) { m8[d] = 0.9f * u8[d] * ru + 0.1f * bp[d]; sqm += m8[d] * m8[d]; }
    float nm = wred(sqm) * 0.25f;
    float rm = 1.f / (sqrtf(nm) + EPSF);
    float nrm2 = sqrtf(nm) * rm;   // ~1
    float rf = rm / (nrm2 + EPSF);
    if (sub == 0) {
        float4 o0 = make_float4(m8[0] * rf, m8[1] * rf, m8[2] * rf, m8[3] * rf);
        float4 o1 = make_float4(m8[4] * rf, m8[5] * rf, m8[6] * rf, m8[7] * rf);
        *(float4*)(out + i * 64 + l8 * 8)     = o0;
        *(float4*)(out + i * 64 + l8 * 8 + 4) = o1;
    }
}

extern "C" void kernel_launch(void* const* d_in, const int* in_sizes, int n_in,
                              void* d_out, int out_size) {
    const float* x  = (const float*)d_in[0];
    const int*   ei = (const int*)d_in[1];
    const float* Ws = (const float*)d_in[2];
    const float* Wn = (const float*)d_in[3];
    const float* b  = (const float*)d_in[4];
    float* out = (float*)d_out;

    k_prep<<<NN / 256, 256>>>(Ws, Wn);
    k_transform<<<NN / 8, 128>>>(x);
    k_edge<<<NE / 64, 256>>>(ei);
    k_agg<<<NN / 4, 128>>>(b, out);
}

// round 11
// speedup vs baseline: 1.1890x; 1.0723x over previous
#include <cuda_runtime.h>
#include <cuda_fp16.h>

#define NN 12288
#define NE 393216
#define EPSF 1e-8f
#define CAPN 192          // fixed bucket capacity per node (deg ~ Poisson(64))
#define LCAP 16           // per-warp conflict-list capacity (dups ~0.12/node)

// ---- scratch (static device globals; no allocation in kernel_launch) ----
__device__ float4 g_wp[64 * 32];                // packed (WsT, WsT+32, WnT, WnT+32)
__device__ float  g_bp[64];                     // 0.1-blend bias projection (normalized)
__device__ __half g_xnh[NN * 64];               // fp16 x/||x|| (edge cosines)
__device__ __half g_anh[NN * 64];               // fp16 normalize(x @ Wn^T)
__device__ float  g_sf[NN * 64];                // fp32 normalize(x @ Ws^T)
__device__ unsigned int g_cur[NN];              // per-node fill counters
__device__ unsigned int g_pay[NN * CAPN];       // packed (fp16(w)<<16 | j14)

__device__ __forceinline__ float wred(float v) {
#pragma unroll
    for (int o = 16; o; o >>= 1) v += __shfl_xor_sync(0xffffffffu, v, o);
    return v;
}
__device__ __forceinline__ float payw(unsigned int p) {
    return __half2float(__ushort_as_half((unsigned short)(p >> 16)));
}

// ---------------------------------------------------------------------------
// Prep: repack W (L1-resident afterwards), zero g_cur, precompute bias proj.
// ---------------------------------------------------------------------------
__global__ void k_prep(const float* __restrict__ Ws, const float* __restrict__ Wn,
                       const float* __restrict__ bias) {
    int t = blockIdx.x * blockDim.x + threadIdx.x;
    if (t < NN) g_cur[t] = 0u;
    if (t < 2048) {
        int k = t >> 5, l = t & 31;
        g_wp[k * 32 + l] = make_float4(Ws[l * 64 + k], Ws[(l + 32) * 64 + k],
                                       Wn[l * 64 + k], Wn[(l + 32) * 64 + k]);
    }
    if (blockIdx.x == 0 && threadIdx.x < 32) {
        int lane = threadIdx.x;
        float2 bv = ((const float2*)bias)[lane];
        float nb = sqrtf(wred(bv.x * bv.x + bv.y * bv.y) + 1.0f);  // ||[bias,1]||
        ((float2*)g_bp)[lane] = make_float2(bv.x / nb, bv.y / nb);
    }
}

// ---------------------------------------------------------------------------
// 2 nodes per warp, 128-thread blocks. W via coalesced LDG.128 (L1-hit),
// x broadcast from tiny per-warp smem.
// ---------------------------------------------------------------------------
__global__ __launch_bounds__(128) void k_transform(const float* __restrict__ x) {
    __shared__ float sx[4][2][64];     // [warp][node][k]
    int warp = threadIdx.x >> 5, lane = threadIdx.x & 31;
    int i0 = blockIdx.x * 8 + warp * 2;

    float xa0[2], xa1[2];
#pragma unroll
    for (int n = 0; n < 2; n++) {
        xa0[n] = x[(i0 + n) * 64 + lane];
        xa1[n] = x[(i0 + n) * 64 + 32 + lane];
        sx[warp][n][lane]      = xa0[n];
        sx[warp][n][32 + lane] = xa1[n];
    }
    __syncwarp();

    float s0[2] = {0, 0}, s1[2] = {0, 0}, a0[2] = {0, 0}, a1[2] = {0, 0};
#pragma unroll
    for (int kb = 0; kb < 16; kb++) {
        float4 w0 = __ldg(&g_wp[(kb * 4 + 0) * 32 + lane]);
        float4 w1 = __ldg(&g_wp[(kb * 4 + 1) * 32 + lane]);
        float4 w2 = __ldg(&g_wp[(kb * 4 + 2) * 32 + lane]);
        float4 w3 = __ldg(&g_wp[(kb * 4 + 3) * 32 + lane]);
#pragma unroll
        for (int n = 0; n < 2; n++) {
            float4 xq = *(const float4*)&sx[warp][n][kb * 4];  // LDS.128 broadcast
            s0[n] += xq.x * w0.x + xq.y * w1.x + xq.z * w2.x + xq.w * w3.x;
            s1[n] += xq.x * w0.y + xq.y * w1.y + xq.z * w2.y + xq.w * w3.y;
            a0[n] += xq.x * w0.z + xq.y * w1.z + xq.z * w2.z + xq.w * w3.z;
            a1[n] += xq.x * w0.w + xq.y * w1.w + xq.z * w2.w + xq.w * w3.w;
        }
    }
#pragma unroll
    for (int n = 0; n < 2; n++) {
        int i = i0 + n;
        float nx = wred(xa0[n] * xa0[n] + xa1[n] * xa1[n]);
        float ns = wred(s0[n] * s0[n] + s1[n] * s1[n]);
        float na = wred(a0[n] * a0[n] + a1[n] * a1[n]);
        float rx = 1.f / sqrtf(nx);
        float rs = 1.f / (sqrtf(ns) + EPSF);
        float ra = 1.f / (sqrtf(na) + EPSF);
        g_xnh[i * 64 + lane]      = __float2half_rn(xa0[n] * rx);
        g_xnh[i * 64 + 32 + lane] = __float2half_rn(xa1[n] * rx);
        g_anh[i * 64 + lane]      = __float2half_rn(a0[n] * ra);
        g_anh[i * 64 + 32 + lane] = __float2half_rn(a1[n] * ra);
        g_sf[i * 64 + lane]       = s0[n] * rs;
        g_sf[i * 64 + 32 + lane]  = s1[n] * rs;
    }
}

// ---------------------------------------------------------------------------
// 8 edges per warp, 4 lanes per edge. Cosine weight, then scatter both
// directed incidences as 4-byte payloads (fp16(w)<<16 | j). All writers to
// the same (i,j) produce bitwise-identical w (cos symmetric), so last-write-
// wins == any-write-wins; no ordering key needed.
// ---------------------------------------------------------------------------
__global__ __launch_bounds__(256) void k_edge(const int* __restrict__ ei) {
    int warp = threadIdx.x >> 5, lane = threadIdx.x & 31;
    int sub = lane >> 2, l4 = lane & 3;
    int k = blockIdx.x * 64 + warp * 8 + sub;
    int r = __ldg(&ei[k]);
    int c = __ldg(&ei[NE + k]);
    const __half* pr = g_xnh + r * 64 + l4 * 16;
    const __half* pc = g_xnh + c * 64 + l4 * 16;
    uint4 ur0 = *(const uint4*)(pr);
    uint4 ur1 = *(const uint4*)(pr + 8);
    uint4 uc0 = *(const uint4*)(pc);
    uint4 uc1 = *(const uint4*)(pc + 8);
    const __half2* hr0 = (const __half2*)&ur0;
    const __half2* hr1 = (const __half2*)&ur1;
    const __half2* hc0 = (const __half2*)&uc0;
    const __half2* hc1 = (const __half2*)&uc1;
    float d = 0.f;
#pragma unroll
    for (int q = 0; q < 4; q++) {
        float2 a0 = __half22float2(hr0[q]);
        float2 b0 = __half22float2(hc0[q]);
        float2 a1 = __half22float2(hr1[q]);
        float2 b1 = __half22float2(hc1[q]);
        d += a0.x * b0.x + a0.y * b0.y + a1.x * b1.x + a1.y * b1.y;
    }
#pragma unroll
    for (int o = 2; o; o >>= 1) d += __shfl_xor_sync(0xffffffffu, d, o);
    if (l4 == 0) {
        float w = fminf(fmaxf((d + 1.f) * 0.5f, 0.1f), 0.9f);
        unsigned int hw = (unsigned int)__half_as_ushort(__float2half_rn(w)) << 16;
        unsigned int p = atomicAdd(&g_cur[r], 1u);
        if (p < CAPN) g_pay[r * CAPN + p] = hw | (unsigned)c;
        unsigned int q2 = atomicAdd(&g_cur[c], 1u);
        if (q2 < CAPN) g_pay[c * CAPN + q2] = hw | (unsigned)r;
    }
}

// ---------------------------------------------------------------------------
// One warp per node, 128-thread blocks. Phase A: payload staging + bitmap
// dup-detect. Phase B: fp16 gather, 16 entries/iter (4 independent LDG.128
// chains), 8 lanes/entry. Duplicate fixup: all dup entries of (i,j) share w,
// so subtract (cnt-1)*w*f_j — counted from smem only.
// ---------------------------------------------------------------------------
__global__ __launch_bounds__(128, 12) void k_agg(float* __restrict__ out) {
    __shared__ unsigned int bm[4][384];        // 12288-bit presence map per warp
    __shared__ unsigned int spay[4][CAPN + 16];
    __shared__ int cj[4][LCAP];
    __shared__ int ccnt[4];
    int warp = threadIdx.x >> 5, lane = threadIdx.x & 31;
    int sub = lane >> 3, l8 = lane & 7;
    int i = blockIdx.x * 4 + warp;

#pragma unroll
    for (int t = lane; t < 384; t += 32) bm[warp][t] = 0u;
    if (lane == 0) ccnt[warp] = 0;
    __syncwarp();

    int deg = (int)min(g_cur[i], (unsigned)CAPN);
    int selfF = 0;

    // Phase A: stage payloads + duplicate detection
    for (int base = 0; base < deg; base += 32) {
        int e = base + lane;
        if (e < deg) {
            unsigned int p = __ldg(&g_pay[i * CAPN + e]);
            spay[warp][e] = p;
            unsigned int j = p & 0x3FFFu;
            if (j == (unsigned)i) selfF = 1;
            unsigned int old = atomicOr(&bm[warp][j >> 5], 1u << (j & 31));
            if (old & (1u << (j & 31))) {
                int idx = atomicAdd(&ccnt[warp], 1);
                if (idx < LCAP) cj[warp][idx] = (int)j;
            }
        }
    }
    if (lane < 16) spay[warp][deg + lane] = 0u;   // zero-weight padding
    int hasSelf = (__ballot_sync(0xffffffffu, selfF) != 0u);
    __syncwarp();

    // Phase B: 16 entries/iter; lane handles entries t+sub, t+4+sub, t+8+sub, t+12+sub
    float acc[8] = {0, 0, 0, 0, 0, 0, 0, 0};
    for (int t = 0; t < deg; t += 16) {
        unsigned int pA = spay[warp][t + sub];
        unsigned int pB = spay[warp][t + 4 + sub];
        unsigned int pC = spay[warp][t + 8 + sub];
        unsigned int pD = spay[warp][t + 12 + sub];
        float wA = payw(pA), wB = payw(pB), wC = payw(pC), wD = payw(pD);
        uint4 uA = *(const uint4*)(g_anh + (pA & 0x3FFFu) * 64 + l8 * 8);
        uint4 uB = *(const uint4*)(g_anh + (pB & 0x3FFFu) * 64 + l8 * 8);
        uint4 uC = *(const uint4*)(g_anh + (pC & 0x3FFFu) * 64 + l8 * 8);
        uint4 uD = *(const uint4*)(g_anh + (pD & 0x3FFFu) * 64 + l8 * 8);
        const __half2* hA = (const __half2*)&uA;
        const __half2* hB = (const __half2*)&uB;
        const __half2* hC = (const __half2*)&uC;
        const __half2* hD = (const __half2*)&uD;
#pragma unroll
        for (int q = 0; q < 4; q++) {
            float2 fA = __half22float2(hA[q]);
            float2 fB = __half22float2(hB[q]);
            float2 fC = __half22float2(hC[q]);
            float2 fD = __half22float2(hD[q]);
            acc[2 * q]     += wA * fA.x + wB * fB.x + wC * fC.x + wD * fD.x;
            acc[2 * q + 1] += wA * fA.y + wB * fB.y + wC * fC.y + wD * fD.y;
        }
    }
#pragma unroll
    for (int d = 0; d < 8; d++) {
        acc[d] += __shfl_xor_sync(0xffffffffu, acc[d], 8);
        acc[d] += __shfl_xor_sync(0xffffffffu, acc[d], 16);
    }

    // fixup for conflicted j's (rare): dup entries share w -> subtract (cnt-1)*w
    int cc = min(ccnt[warp], LCAP);
    for (int t = 0; t < cc; t++) {
        int j = cj[warp][t];
        bool seen = false;                 // same j pushed (c-1) times for c dups
        for (int u2 = 0; u2 < t; u2++) if (cj[warp][u2] == j) { seen = true; break; }
        if (seen) continue;
        int cnt = 0;
        unsigned int pw = 0u;
        for (int base = 0; base < deg; base += 32) {
            int e = base + lane;
            unsigned int p = (e < deg) ? spay[warp][e] : 0u;
            bool m = (e < deg) && ((p & 0x3FFFu) == (unsigned)j);
            if (m) { cnt++; pw = p; }
        }
        cnt = __reduce_add_sync(0xffffffffu, cnt);
        pw  = __reduce_max_sync(0xffffffffu, pw);   // all matches identical
        float corr = (float)(cnt - 1) * payw(pw);
        uint4 u = *(const uint4*)(g_anh + j * 64 + l8 * 8);
        const __half2* h = (const __half2*)&u;
#pragma unroll
        for (int q = 0; q < 4; q++) {
            float2 f = __half22float2(h[q]);
            acc[2 * q]     -= corr * f.x;
            acc[2 * q + 1] -= corr * f.y;
        }
    }
    if (!hasSelf) {   // eye diagonal survives only when no edge overwrote it
        uint4 u = *(const uint4*)(g_anh + i * 64 + l8 * 8);
        const __half2* h = (const __half2*)&u;
#pragma unroll
        for (int q = 0; q < 4; q++) {
            float2 f = __half22float2(h[q]);
            acc[2 * q]     += f.x;
            acc[2 * q + 1] += f.y;
        }
    }

    // epilogue (dims replicated 4x across sub-groups: norms = wred(.)/4)
    float bp[8];
    {
        float4 b0 = *(const float4*)(g_bp + l8 * 8);
        float4 b1 = *(const float4*)(g_bp + l8 * 8 + 4);
        bp[0] = b0.x; bp[1] = b0.y; bp[2] = b0.z; bp[3] = b0.w;
        bp[4] = b1.x; bp[5] = b1.y; bp[6] = b1.z; bp[7] = b1.w;
    }
    float sq = 0.f;
#pragma unroll
    for (int d = 0; d < 8; d++) sq += acc[d] * acc[d];
    float na = wred(sq) * 0.25f;
    float rn = 1.f / (sqrtf(na) + EPSF);

    float sv[8];
    {
        float4 s0 = *(const float4*)(g_sf + i * 64 + l8 * 8);
        float4 s1 = *(const float4*)(g_sf + i * 64 + l8 * 8 + 4);
        sv[0] = s0.x; sv[1] = s0.y; sv[2] = s0.z; sv[3] = s0.w;
        sv[4] = s1.x; sv[5] = s1.y; sv[6] = s1.z; sv[7] = s1.w;
    }
    float u8[8]; float squ = 0.f;
#pragma unroll
    for (int d = 0; d < 8; d++) { u8[d] = 0.5f * (sv[d] + acc[d] * rn); squ += u8[d] * u8[d]; }
    float nu = wred(squ) * 0.25f;
    float ru = 1.f / (sqrtf(nu) + EPSF);
    float m8[8]; float sqm = 0.f;
#pragma unroll
    for (int d = 0; d < 8; d++) { m8[d] = 0.9f * u8[d] * ru + 0.1f * bp[d]; sqm += m8[d] * m8[d]; }
    float nm = wred(sqm) * 0.25f;
    float rm = 1.f / (sqrtf(nm) + EPSF);
    float nrm2 = sqrtf(nm) * rm;   // ~1
    float rf = rm / (nrm2 + EPSF);
    if (sub == 0) {
        float4 o0 = make_float4(m8[0] * rf, m8[1] * rf, m8[2] * rf, m8[3] * rf);
        float4 o1 = make_float4(m8[4] * rf, m8[5] * rf, m8[6] * rf, m8[7] * rf);
        *(float4*)(out + i * 64 + l8 * 8)     = o0;
        *(float4*)(out + i * 64 + l8 * 8 + 4) = o1;
    }
}

extern "C" void kernel_launch(void* const* d_in, const int* in_sizes, int n_in,
                              void* d_out, int out_size) {
    const float* x  = (const float*)d_in[0];
    const int*   ei = (const int*)d_in[1];
    const float* Ws = (const float*)d_in[2];
    const float* Wn = (const float*)d_in[3];
    const float* b  = (const float*)d_in[4];
    float* out = (float*)d_out;

    k_prep<<<NN / 256, 256>>>(Ws, Wn, b);
    k_transform<<<NN / 8, 128>>>(x);
    k_edge<<<NE / 64, 256>>>(ei);
    k_agg<<<NN / 4, 128>>>(out);
}

// round 13
// speedup vs baseline: 1.2932x; 1.0876x over previous
#include <cuda_runtime.h>
#include <cuda_fp16.h>

#define NN 12288
#define NE 393216
#define EPSF 1e-8f
#define CAPN 192          // fixed bucket capacity per node (deg ~ Poisson(64))
#define LCAP 16           // per-warp conflict-list capacity (dups ~0.12/node)

// ---- scratch (static device globals; no allocation in kernel_launch) ----
__device__ float4 g_wp[64 * 32];                // packed (WsT, WsT+32, WnT, WnT+32)
__device__ float  g_bp[64];                     // 0.1-blend bias projection (normalized)
__device__ __half g_xnh[NN * 64];               // fp16 x/||x|| (edge cosines)
__device__ __half g_anh[NN * 64];               // fp16 normalize(x @ Wn^T)
__device__ float  g_sf[NN * 64];                // fp32 normalize(x @ Ws^T)
__device__ unsigned int g_cur[NN];              // per-node fill counters
__device__ unsigned int g_pay[NN * CAPN];       // packed (fp16(w)<<16 | j14)

__device__ __forceinline__ float wred(float v) {
#pragma unroll
    for (int o = 16; o; o >>= 1) v += __shfl_xor_sync(0xffffffffu, v, o);
    return v;
}
__device__ __forceinline__ float payw(unsigned int p) {
    return __half2float(__ushort_as_half((unsigned short)(p >> 16)));
}

// ---------------------------------------------------------------------------
// Pre: x-hat (fp16) with one float4 per thread + 16-lane row reduction
// (high MLP, fully coalesced), W repack, g_cur zero, bias projection.
// ---------------------------------------------------------------------------
__global__ __launch_bounds__(128) void k_pre(const float* __restrict__ x,
                                             const float* __restrict__ Ws,
                                             const float* __restrict__ Wn,
                                             const float* __restrict__ bias) {
    int t = blockIdx.x * 128 + threadIdx.x;
    if (t < NN) g_cur[t] = 0u;
    if (t < 2048) {
        int k = t >> 5, l = t & 31;
        g_wp[k * 32 + l] = make_float4(Ws[l * 64 + k], Ws[(l + 32) * 64 + k],
                                       Wn[l * 64 + k], Wn[(l + 32) * 64 + k]);
    }
    if (blockIdx.x == 0 && threadIdx.x < 32) {
        int lane = threadIdx.x;
        float2 bv = ((const float2*)bias)[lane];
        float nb = sqrtf(wred(bv.x * bv.x + bv.y * bv.y) + 1.0f);  // ||[bias,1]||
        ((float2*)g_bp)[lane] = make_float2(bv.x / nb, bv.y / nb);
    }
    // x normalization: thread owns 4 consecutive floats of one row
    float4 xv = *(const float4*)(x + t * 4);
    float ss = xv.x * xv.x + xv.y * xv.y + xv.z * xv.z + xv.w * xv.w;
#pragma unroll
    for (int o = 8; o; o >>= 1) ss += __shfl_xor_sync(0xffffffffu, ss, o);
    float rx = rsqrtf(ss);
    __half2* dst = (__half2*)(g_xnh + t * 4);
    dst[0] = __floats2half2_rn(xv.x * rx, xv.y * rx);
    dst[1] = __floats2half2_rn(xv.z * rx, xv.w * rx);
}

// ---------------------------------------------------------------------------
// Mixed kernel: roles interleaved by bid%9 so gemv (FMA-bound) and edge
// (L2/scatter-bound) blocks are co-resident in every wave.
//   r==0: gemv block g in [0,768): 16 nodes (8 warps x 2)
//   else: edge block g*8+(r-1) in [0,6144): 64 edges (8 warps x 8)
// ---------------------------------------------------------------------------
__global__ __launch_bounds__(256) void k_mix(const float* __restrict__ x,
                                             const int* __restrict__ ei) {
    int warp = threadIdx.x >> 5, lane = threadIdx.x & 31;
    int g = blockIdx.x / 9, r9 = blockIdx.x % 9;

    if (r9 == 0) {
        // ---- GEMV role ----
        __shared__ float sx[8][2][64];
        int i0 = g * 16 + warp * 2;
        float xa0[2], xa1[2];
#pragma unroll
        for (int n = 0; n < 2; n++) {
            xa0[n] = x[(i0 + n) * 64 + lane];
            xa1[n] = x[(i0 + n) * 64 + 32 + lane];
            sx[warp][n][lane]      = xa0[n];
            sx[warp][n][32 + lane] = xa1[n];
        }
        __syncwarp();
        float s0[2] = {0, 0}, s1[2] = {0, 0}, a0[2] = {0, 0}, a1[2] = {0, 0};
#pragma unroll
        for (int kb = 0; kb < 16; kb++) {
            float4 w0 = __ldg(&g_wp[(kb * 4 + 0) * 32 + lane]);
            float4 w1 = __ldg(&g_wp[(kb * 4 + 1) * 32 + lane]);
            float4 w2 = __ldg(&g_wp[(kb * 4 + 2) * 32 + lane]);
            float4 w3 = __ldg(&g_wp[(kb * 4 + 3) * 32 + lane]);
#pragma unroll
            for (int n = 0; n < 2; n++) {
                float4 xq = *(const float4*)&sx[warp][n][kb * 4];  // LDS.128 broadcast
                s0[n] += xq.x * w0.x + xq.y * w1.x + xq.z * w2.x + xq.w * w3.x;
                s1[n] += xq.x * w0.y + xq.y * w1.y + xq.z * w2.y + xq.w * w3.y;
                a0[n] += xq.x * w0.z + xq.y * w1.z + xq.z * w2.z + xq.w * w3.z;
                a1[n] += xq.x * w0.w + xq.y * w1.w + xq.z * w2.w + xq.w * w3.w;
            }
        }
#pragma unroll
        for (int n = 0; n < 2; n++) {
            int i = i0 + n;
            float ns = wred(s0[n] * s0[n] + s1[n] * s1[n]);
            float na = wred(a0[n] * a0[n] + a1[n] * a1[n]);
            float rs = 1.f / (sqrtf(ns) + EPSF);
            float ra = 1.f / (sqrtf(na) + EPSF);
            g_anh[i * 64 + lane]      = __float2half_rn(a0[n] * ra);
            g_anh[i * 64 + 32 + lane] = __float2half_rn(a1[n] * ra);
            g_sf[i * 64 + lane]       = s0[n] * rs;
            g_sf[i * 64 + 32 + lane]  = s1[n] * rs;
        }
    } else {
        // ---- Edge role: 8 edges/warp, 4 lanes/edge ----
        int eb = g * 8 + (r9 - 1);
        int sub = lane >> 2, l4 = lane & 3;
        int k = eb * 64 + warp * 8 + sub;
        int rr = __ldg(&ei[k]);
        int cc = __ldg(&ei[NE + k]);
        const __half* pr = g_xnh + rr * 64 + l4 * 16;
        const __half* pc = g_xnh + cc * 64 + l4 * 16;
        uint4 ur0 = *(const uint4*)(pr);
        uint4 ur1 = *(const uint4*)(pr + 8);
        uint4 uc0 = *(const uint4*)(pc);
        uint4 uc1 = *(const uint4*)(pc + 8);
        const __half2* hr0 = (const __half2*)&ur0;
        const __half2* hr1 = (const __half2*)&ur1;
        const __half2* hc0 = (const __half2*)&uc0;
        const __half2* hc1 = (const __half2*)&uc1;
        float d = 0.f;
#pragma unroll
        for (int q = 0; q < 4; q++) {
            float2 a0 = __half22float2(hr0[q]);
            float2 b0 = __half22float2(hc0[q]);
            float2 a1 = __half22float2(hr1[q]);
            float2 b1 = __half22float2(hc1[q]);
            d += a0.x * b0.x + a0.y * b0.y + a1.x * b1.x + a1.y * b1.y;
        }
#pragma unroll
        for (int o = 2; o; o >>= 1) d += __shfl_xor_sync(0xffffffffu, d, o);
        if (l4 == 0) {
            float w = fminf(fmaxf((d + 1.f) * 0.5f, 0.1f), 0.9f);
            unsigned int hw = (unsigned int)__half_as_ushort(__float2half_rn(w)) << 16;
            unsigned int p = atomicAdd(&g_cur[rr], 1u);
            if (p < CAPN) g_pay[rr * CAPN + p] = hw | (unsigned)cc;
            unsigned int q2 = atomicAdd(&g_cur[cc], 1u);
            if (q2 < CAPN) g_pay[cc * CAPN + q2] = hw | (unsigned)rr;
        }
    }
}

// ---------------------------------------------------------------------------
// One warp per node, 128-thread blocks. Phase A: payload staging + bitmap
// dup-detect. Phase B: fp16 gather, 16 entries/iter (4 independent LDG.128
// chains), 8 lanes/entry. Duplicate fixup: all dup entries of (i,j) share w,
// so subtract (cnt-1)*w*f_j — counted from smem only.
// ---------------------------------------------------------------------------
__global__ __launch_bounds__(128, 12) void k_agg(float* __restrict__ out) {
    __shared__ unsigned int bm[4][384];        // 12288-bit presence map per warp
    __shared__ unsigned int spay[4][CAPN + 16];
    __shared__ int cj[4][LCAP];
    __shared__ int ccnt[4];
    int warp = threadIdx.x >> 5, lane = threadIdx.x & 31;
    int sub = lane >> 3, l8 = lane & 7;
    int i = blockIdx.x * 4 + warp;

#pragma unroll
    for (int t = lane; t < 384; t += 32) bm[warp][t] = 0u;
    if (lane == 0) ccnt[warp] = 0;
    __syncwarp();

    int deg = (int)min(g_cur[i], (unsigned)CAPN);
    int selfF = 0;

    // Phase A: stage payloads + duplicate detection
    for (int base = 0; base < deg; base += 32) {
        int e = base + lane;
        if (e < deg) {
            unsigned int p = __ldg(&g_pay[i * CAPN + e]);
            spay[warp][e] = p;
            unsigned int j = p & 0x3FFFu;
            if (j == (unsigned)i) selfF = 1;
            unsigned int old = atomicOr(&bm[warp][j >> 5], 1u << (j & 31));
            if (old & (1u << (j & 31))) {
                int idx = atomicAdd(&ccnt[warp], 1);
                if (idx < LCAP) cj[warp][idx] = (int)j;
            }
        }
    }
    if (lane < 16) spay[warp][deg + lane] = 0u;   // zero-weight padding
    int hasSelf = (__ballot_sync(0xffffffffu, selfF) != 0u);
    __syncwarp();

    // Phase B: 16 entries/iter; lane handles entries t+sub, t+4+sub, t+8+sub, t+12+sub
    float acc[8] = {0, 0, 0, 0, 0, 0, 0, 0};
    for (int t = 0; t < deg; t += 16) {
        unsigned int pA = spay[warp][t + sub];
        unsigned int pB = spay[warp][t + 4 + sub];
        unsigned int pC = spay[warp][t + 8 + sub];
        unsigned int pD = spay[warp][t + 12 + sub];
        float wA = payw(pA), wB = payw(pB), wC = payw(pC), wD = payw(pD);
        uint4 uA = *(const uint4*)(g_anh + (pA & 0x3FFFu) * 64 + l8 * 8);
        uint4 uB = *(const uint4*)(g_anh + (pB & 0x3FFFu) * 64 + l8 * 8);
        uint4 uC = *(const uint4*)(g_anh + (pC & 0x3FFFu) * 64 + l8 * 8);
        uint4 uD = *(const uint4*)(g_anh + (pD & 0x3FFFu) * 64 + l8 * 8);
        const __half2* hA = (const __half2*)&uA;
        const __half2* hB = (const __half2*)&uB;
        const __half2* hC = (const __half2*)&uC;
        const __half2* hD = (const __half2*)&uD;
#pragma unroll
        for (int q = 0; q < 4; q++) {
            float2 fA = __half22float2(hA[q]);
            float2 fB = __half22float2(hB[q]);
            float2 fC = __half22float2(hC[q]);
            float2 fD = __half22float2(hD[q]);
            acc[2 * q]     += wA * fA.x + wB * fB.x + wC * fC.x + wD * fD.x;
            acc[2 * q + 1] += wA * fA.y + wB * fB.y + wC * fC.y + wD * fD.y;
        }
    }
#pragma unroll
    for (int d = 0; d < 8; d++) {
        acc[d] += __shfl_xor_sync(0xffffffffu, acc[d], 8);
        acc[d] += __shfl_xor_sync(0xffffffffu, acc[d], 16);
    }

    // fixup for conflicted j's (rare): dup entries share w -> subtract (cnt-1)*w
    int cc = min(ccnt[warp], LCAP);
    for (int t = 0; t < cc; t++) {
        int j = cj[warp][t];
        bool seen = false;                 // same j pushed (c-1) times for c dups
        for (int u2 = 0; u2 < t; u2++) if (cj[warp][u2] == j) { seen = true; break; }
        if (seen) continue;
        int cnt = 0;
        unsigned int pw = 0u;
        for (int base = 0; base < deg; base += 32) {
            int e = base + lane;
            unsigned int p = (e < deg) ? spay[warp][e] : 0u;
            bool m = (e < deg) && ((p & 0x3FFFu) == (unsigned)j);
            if (m) { cnt++; pw = p; }
        }
        cnt = __reduce_add_sync(0xffffffffu, cnt);
        pw  = __reduce_max_sync(0xffffffffu, pw);   // all matches identical
        float corr = (float)(cnt - 1) * payw(pw);
        uint4 u = *(const uint4*)(g_anh + j * 64 + l8 * 8);
        const __half2* h = (const __half2*)&u;
#pragma unroll
        for (int q = 0; q < 4; q++) {
            float2 f = __half22float2(h[q]);
            acc[2 * q]     -= corr * f.x;
            acc[2 * q + 1] -= corr * f.y;
        }
    }
    if (!hasSelf) {   // eye diagonal survives only when no edge overwrote it
        uint4 u = *(const uint4*)(g_anh + i * 64 + l8 * 8);
        const __half2* h = (const __half2*)&u;
#pragma unroll
        for (int q = 0; q < 4; q++) {
            float2 f = __half22float2(h[q]);
            acc[2 * q]     += f.x;
            acc[2 * q + 1] += f.y;
        }
    }

    // epilogue (dims replicated 4x across sub-groups: norms = wred(.)/4)
    float bp[8];
    {
        float4 b0 = *(const float4*)(g_bp + l8 * 8);
        float4 b1 = *(const float4*)(g_bp + l8 * 8 + 4);
        bp[0] = b0.x; bp[1] = b0.y; bp[2] = b0.z; bp[3] = b0.w;
        bp[4] = b1.x; bp[5] = b1.y; bp[6] = b1.z; bp[7] = b1.w;
    }
    float sq = 0.f;
#pragma unroll
    for (int d = 0; d < 8; d++) sq += acc[d] * acc[d];
    float na = wred(sq) * 0.25f;
    float rn = 1.f / (sqrtf(na) + EPSF);

    float sv[8];
    {
        float4 s0 = *(const float4*)(g_sf + i * 64 + l8 * 8);
        float4 s1 = *(const float4*)(g_sf + i * 64 + l8 * 8 + 4);
        sv[0] = s0.x; sv[1] = s0.y; sv[2] = s0.z; sv[3] = s0.w;
        sv[4] = s1.x; sv[5] = s1.y; sv[6] = s1.z; sv[7] = s1.w;
    }
    float u8[8]; float squ = 0.f;
#pragma unroll
    for (int d = 0; d < 8; d++) { u8[d] = 0.5f * (sv[d] + acc[d] * rn); squ += u8[d] * u8[d]; }
    float nu = wred(squ) * 0.25f;
    float ru = 1.f / (sqrtf(nu) + EPSF);
    float m8[8]; float sqm = 0.f;
#pragma unroll
    for (int d = 0; d < 8; d++) { m8[d] = 0.9f * u8[d] * ru + 0.1f * bp[d]; sqm += m8[d] * m8[d]; }
    float nm = wred(sqm) * 0.25f;
    float rm = 1.f / (sqrtf(nm) + EPSF);
    float nrm2 = sqrtf(nm) * rm;   // ~1
    float rf = rm / (nrm2 + EPSF);
    if (sub == 0) {
        float4 o0 = make_float4(m8[0] * rf, m8[1] * rf, m8[2] * rf, m8[3] * rf);
        float4 o1 = make_float4(m8[4] * rf, m8[5] * rf, m8[6] * rf, m8[7] * rf);
        *(float4*)(out + i * 64 + l8 * 8)     = o0;
        *(float4*)(out + i * 64 + l8 * 8 + 4) = o1;
    }
}

extern "C" void kernel_launch(void* const* d_in, const int* in_sizes, int n_in,
                              void* d_out, int out_size) {
    const float* x  = (const float*)d_in[0];
    const int*   ei = (const int*)d_in[1];
    const float* Ws = (const float*)d_in[2];
    const float* Wn = (const float*)d_in[3];
    const float* b  = (const float*)d_in[4];
    float* out = (float*)d_out;

    k_pre<<<NN * 64 / 4 / 128, 128>>>(x, Ws, Wn, b);
    k_mix<<<6912, 256>>>(x, ei);
    k_agg<<<NN / 4, 128>>>(out);
}